// round 2
// baseline (speedup 1.0000x reference)
#include <cuda_runtime.h>
#include <cuda_bf16.h>
#include <mma.h>
#include <math.h>

using namespace nvcuda;

// ---------------- problem constants ----------------
#define BB   256      // batch
#define CC   256      // channels
#define NN   196      // tokens (14*14)
#define NH   8        // heads
#define DD   32       // head dim
#define CM   2048     // ffn hidden
#define MROWS (BB*NN) // 50176
#define EPSBN 1e-5f

// ---------------- scratch (device globals; no allocations allowed) ----------------
__device__ float g_t [(size_t)MROWS*CC];      // tokens [B*N, C]
__device__ float g_qkv[(size_t)3*BB*NH*NN*DD]; // [part, b, h, n, d]
__device__ float g_o [(size_t)MROWS*CC];      // attention out [B*N, C]
__device__ float g_t2[(size_t)MROWS*CC];      // after repbn1
__device__ float g_h [(size_t)MROWS*CM];      // ffn hidden
__device__ float g_t3[(size_t)MROWS*CC];      // before final transpose

// ---------------- transposes ----------------
__global__ void transpose_in(const float* __restrict__ x, float* __restrict__ t)
{
    __shared__ float tile[32][33];
    int b  = blockIdx.z;
    int n0 = blockIdx.x * 32;
    int c0 = blockIdx.y * 32;
    int tx = threadIdx.x, ty = threadIdx.y;
#pragma unroll
    for (int i = 0; i < 4; i++) {
        int c = c0 + ty + 8*i;
        int n = n0 + tx;
        if (n < NN) tile[ty + 8*i][tx] = x[((size_t)b*CC + c)*NN + n];
    }
    __syncthreads();
#pragma unroll
    for (int i = 0; i < 4; i++) {
        int n = n0 + ty + 8*i;
        int c = c0 + tx;
        if (n < NN) t[((size_t)b*NN + n)*CC + c] = tile[tx][ty + 8*i];
    }
}

__global__ void transpose_out(const float* __restrict__ t, float* __restrict__ x)
{
    __shared__ float tile[32][33];
    int b  = blockIdx.z;
    int n0 = blockIdx.x * 32;
    int c0 = blockIdx.y * 32;
    int tx = threadIdx.x, ty = threadIdx.y;
#pragma unroll
    for (int i = 0; i < 4; i++) {
        int n = n0 + ty + 8*i;
        int c = c0 + tx;
        if (n < NN) tile[ty + 8*i][tx] = t[((size_t)b*NN + n)*CC + c];
    }
    __syncthreads();
#pragma unroll
    for (int i = 0; i < 4; i++) {
        int c = c0 + ty + 8*i;
        int n = n0 + tx;
        if (n < NN) x[((size_t)b*CC + c)*NN + n] = tile[tx][ty + 8*i];
    }
}

// ---------------- epilogue params ----------------
struct EpiParams {
    const float* bias;
    const float* resid;
    const float* gamma;
    const float* beta;
    const float* rm;
    const float* rv;
    const float* alpha;  // scalar
    const float* saw;    // [B]
    const float* sab;    // [B]
    float*       out;
};

// EPI 0: qkv scatter  | EPI 1: proj + repbn1 | EPI 2: b1 + SpatialSILU | EPI 3: b2 + repbn2
template <int EPI>
__device__ __forceinline__ void apply_epi(int r, int c, float val, const EpiParams& p)
{
    if constexpr (EPI == 0) {
        val += p.bias[c];
        int part = c >> 8;
        int cc   = c & 255;
        int head = cc >> 5;
        int d    = cc & 31;
        int b    = r / NN;
        int n    = r - b * NN;
        size_t PS = (size_t)BB*NH*NN*DD;
        p.out[(size_t)part*PS + (((size_t)(b*NH + head))*NN + n)*DD + d] = val;
    } else if constexpr (EPI == 1 || EPI == 3) {
        val += p.bias[c];
        float tv = p.resid[(size_t)r*CC + c];
        float s  = p.gamma[c] * rsqrtf(p.rv[c] + EPSBN);
        float a  = p.alpha[0];
        float u  = tv + val;
        p.out[(size_t)r*CC + c] = u * (s + a) + (p.beta[c] - p.rm[c]*s);
    } else { // EPI == 2
        val += p.bias[c];
        int b = r / NN;
        float w  = p.saw[b];
        float sb = p.sab[b];
        float wg = w * val + sb;
        float sg = 1.0f / (1.0f + __expf(-wg * val));
        p.out[(size_t)r*CM + c] = val * sg;
    }
}

// ---------------- TF32 tiled GEMM: C[M,N] = A[M,K] @ B[K,N], fused epilogue ----------------
// block tile 128x128, K-step 32, 8 warps (2x4 wmma tiles of 16x16 per warp)
template <int EPI>
__global__ __launch_bounds__(256)
void gemm_tf32(const float* __restrict__ A, const float* __restrict__ Bm,
               int M, int N, int K, EpiParams p)
{
    __shared__ float As[128][36];    // [m][k]
    __shared__ float Bs[32][132];    // [k][n]
    __shared__ float stage[8][256];  // per-warp 16x16 epilogue staging

    int tid  = threadIdx.x;
    int warp = tid >> 5;
    int lane = tid & 31;
    int wm   = warp >> 1;   // 0..3
    int wn   = warp & 1;    // 0..1
    int bn   = blockIdx.x;
    int bm   = blockIdx.y;
    size_t arow0 = (size_t)bm * 128;

    wmma::fragment<wmma::accumulator, 16, 16, 8, float> acc[2][4];
#pragma unroll
    for (int i = 0; i < 2; i++)
#pragma unroll
        for (int j = 0; j < 4; j++)
            wmma::fill_fragment(acc[i][j], 0.0f);

    int ar  = tid >> 3;          // 0..31
    int ac4 = (tid & 7) * 4;     // 0..28
    int br  = tid >> 5;          // 0..7
    int bc4 = (tid & 31) * 4;    // 0..124

    for (int k0 = 0; k0 < K; k0 += 32) {
#pragma unroll
        for (int it = 0; it < 4; it++) {
            float4 v = *(const float4*)&A[(arow0 + ar + it*32)*(size_t)K + k0 + ac4];
            *(float4*)&As[ar + it*32][ac4] = v;
        }
#pragma unroll
        for (int it = 0; it < 4; it++) {
            float4 v = *(const float4*)&Bm[(size_t)(k0 + br + it*8)*N + bn*128 + bc4];
            *(float4*)&Bs[br + it*8][bc4] = v;
        }
        __syncthreads();

#pragma unroll
        for (int kk = 0; kk < 32; kk += 8) {
            wmma::fragment<wmma::matrix_a, 16, 16, 8, wmma::precision::tf32, wmma::row_major> af[2];
            wmma::fragment<wmma::matrix_b, 16, 16, 8, wmma::precision::tf32, wmma::row_major> bf[4];
#pragma unroll
            for (int i = 0; i < 2; i++) {
                wmma::load_matrix_sync(af[i], &As[wm*32 + i*16][kk], 36);
#pragma unroll
                for (int e = 0; e < af[i].num_elements; e++)
                    af[i].x[e] = wmma::__float_to_tf32(af[i].x[e]);
            }
#pragma unroll
            for (int j = 0; j < 4; j++) {
                wmma::load_matrix_sync(bf[j], &Bs[kk][wn*64 + j*16], 132);
#pragma unroll
                for (int e = 0; e < bf[j].num_elements; e++)
                    bf[j].x[e] = wmma::__float_to_tf32(bf[j].x[e]);
            }
#pragma unroll
            for (int i = 0; i < 2; i++)
#pragma unroll
                for (int j = 0; j < 4; j++)
                    wmma::mma_sync(acc[i][j], af[i], bf[j], acc[i][j]);
        }
        __syncthreads();
    }

    // epilogue via per-warp staging
#pragma unroll
    for (int i = 0; i < 2; i++) {
#pragma unroll
        for (int j = 0; j < 4; j++) {
            wmma::store_matrix_sync(&stage[warp][0], acc[i][j], 16, wmma::mem_row_major);
            __syncwarp();
            int r0 = bm*128 + wm*32 + i*16;
            int c0 = bn*128 + wn*64 + j*16;
#pragma unroll
            for (int q = 0; q < 8; q++) {
                int e  = lane*8 + q;
                int rr = e >> 4;
                int cc = e & 15;
                apply_epi<EPI>(r0 + rr, c0 + cc, stage[warp][e], p);
            }
            __syncwarp();
        }
    }
}

// ---------------- attention: one block per (b, head) ----------------
// smem: kst[32][196] (K transposed), vs[196][32], qs[8][4][32], ps[8][196][4]
#define ATTN_SMEM_FLOATS (32*196 + 196*32 + 8*4*32 + 8*196*4)

__global__ __launch_bounds__(256)
void attn_kernel(const float* __restrict__ qkv, float* __restrict__ o)
{
    extern __shared__ float sm[];
    float* kst = sm;                    // [d][j]  d*196 + j
    float* vs  = sm + 32*196;           // [j][d]  j*32 + d
    float* qs  = sm + 2*32*196;         // [w][4][32]
    float* ps  = qs + 8*4*32;           // [w][196][4]

    int bh = blockIdx.x;
    int b  = bh >> 3;
    int h  = bh & 7;
    int tid  = threadIdx.x;
    int w    = tid >> 5;
    int lane = tid & 31;

    size_t PS = (size_t)BB*NH*NN*DD;
    const float* qp = qkv + ((size_t)(b*NH + h))*NN*DD;
    const float* kp = qp + PS;
    const float* vp = qp + 2*PS;

    // load K transposed + V straight
    for (int idx = tid; idx < NN*DD; idx += 256) {
        int j = idx >> 5;
        int d = idx & 31;
        float kv = kp[idx];
        kst[d*NN + j] = kv;
        vs[idx] = vp[idx];
    }
    __syncthreads();

    const float scale = 0.1767766952966369f; // 32^-0.5
    float* qsw = qs + w*128;
    float* psw = ps + w*784;

    int jidx[7]; bool jok[7];
#pragma unroll
    for (int jj = 0; jj < 7; jj++) { jidx[jj] = lane + 32*jj; jok[jj] = jidx[jj] < NN; }

    for (int g = w; g < 49; g += 8) {
        int r0 = g * 4;
        // load 4 query rows into smem
#pragma unroll
        for (int t = 0; t < 4; t++)
            qsw[t*32 + lane] = qp[(size_t)(r0 + t)*DD + lane];
        __syncwarp();

        float s[7][4];
#pragma unroll
        for (int jj = 0; jj < 7; jj++)
#pragma unroll
            for (int r = 0; r < 4; r++) s[jj][r] = 0.0f;

        for (int d = 0; d < 32; d++) {
            float qv0 = qsw[0*32 + d];
            float qv1 = qsw[1*32 + d];
            float qv2 = qsw[2*32 + d];
            float qv3 = qsw[3*32 + d];
            const float* krow = &kst[d*NN];
#pragma unroll
            for (int jj = 0; jj < 7; jj++) {
                float kv = jok[jj] ? krow[jidx[jj]] : 0.0f;
                s[jj][0] += qv0 * kv;
                s[jj][1] += qv1 * kv;
                s[jj][2] += qv2 * kv;
                s[jj][3] += qv3 * kv;
            }
        }

        // softmax per row + write p (normalized) to smem
#pragma unroll
        for (int r = 0; r < 4; r++) {
            float mx = -INFINITY;
#pragma unroll
            for (int jj = 0; jj < 7; jj++) {
                float sv = jok[jj] ? s[jj][r] * scale : -INFINITY;
                s[jj][r] = sv;
                mx = fmaxf(mx, sv);
            }
#pragma unroll
            for (int off = 16; off > 0; off >>= 1)
                mx = fmaxf(mx, __shfl_xor_sync(0xFFFFFFFFu, mx, off));
            float sum = 0.0f;
#pragma unroll
            for (int jj = 0; jj < 7; jj++) {
                float e = jok[jj] ? __expf(s[jj][r] - mx) : 0.0f;
                s[jj][r] = e;
                sum += e;
            }
#pragma unroll
            for (int off = 16; off > 0; off >>= 1)
                sum += __shfl_xor_sync(0xFFFFFFFFu, sum, off);
            float inv = 1.0f / sum;
#pragma unroll
            for (int jj = 0; jj < 7; jj++)
                if (jok[jj]) psw[jidx[jj]*4 + r] = s[jj][r] * inv;
        }
        __syncwarp();

        // P @ V : lane = d
        float a0 = 0.f, a1 = 0.f, a2 = 0.f, a3 = 0.f;
#pragma unroll 4
        for (int j = 0; j < NN; j++) {
            float4 pv = *(const float4*)&psw[j*4];
            float vv = vs[j*32 + lane];
            a0 += pv.x * vv;
            a1 += pv.y * vv;
            a2 += pv.z * vv;
            a3 += pv.w * vv;
        }
        size_t ob = ((size_t)b*NN + r0)*CC + h*DD + lane;
        o[ob + 0*CC] = a0;
        o[ob + 1*CC] = a1;
        o[ob + 2*CC] = a2;
        o[ob + 3*CC] = a3;
        __syncwarp();
    }
}

// ---------------- launch ----------------
extern "C" void kernel_launch(void* const* d_in, const int* in_sizes, int n_in,
                              void* d_out, int out_size)
{
    const float* x      = (const float*)d_in[0];
    const float* W_qkv  = (const float*)d_in[1];
    const float* b_qkv  = (const float*)d_in[2];
    const float* W_proj = (const float*)d_in[3];
    const float* b_proj = (const float*)d_in[4];
    const float* W1     = (const float*)d_in[5];
    const float* b1     = (const float*)d_in[6];
    const float* W2     = (const float*)d_in[7];
    const float* b2     = (const float*)d_in[8];
    const float* sa_w   = (const float*)d_in[9];
    const float* sa_b   = (const float*)d_in[10];
    const float* alpha1 = (const float*)d_in[11];
    const float* gamma1 = (const float*)d_in[12];
    const float* beta1  = (const float*)d_in[13];
    const float* rm1    = (const float*)d_in[14];
    const float* rv1    = (const float*)d_in[15];
    const float* alpha2 = (const float*)d_in[16];
    const float* gamma2 = (const float*)d_in[17];
    const float* beta2  = (const float*)d_in[18];
    const float* rm2    = (const float*)d_in[19];
    const float* rv2    = (const float*)d_in[20];
    float* out = (float*)d_out;

    float *t_p, *qkv_p, *o_p, *t2_p, *h_p, *t3_p;
    cudaGetSymbolAddress((void**)&t_p,   g_t);
    cudaGetSymbolAddress((void**)&qkv_p, g_qkv);
    cudaGetSymbolAddress((void**)&o_p,   g_o);
    cudaGetSymbolAddress((void**)&t2_p,  g_t2);
    cudaGetSymbolAddress((void**)&h_p,   g_h);
    cudaGetSymbolAddress((void**)&t3_p,  g_t3);

    dim3 tb(32, 8);
    dim3 tg(7, 8, BB);

    // 1) x -> t
    transpose_in<<<tg, tb>>>(x, t_p);

    // 2) qkv GEMM (scatter epilogue)
    {
        EpiParams p{};
        p.bias = b_qkv; p.out = qkv_p;
        gemm_tf32<0><<<dim3(768/128, MROWS/128), 256>>>(t_p, W_qkv, MROWS, 768, CC, p);
    }

    // 3) attention
    {
        static int smem_set = 0;
        int smem_bytes = ATTN_SMEM_FLOATS * 4;
        cudaFuncSetAttribute(attn_kernel, cudaFuncAttributeMaxDynamicSharedMemorySize, smem_bytes);
        (void)smem_set;
        attn_kernel<<<BB*NH, 256, smem_bytes>>>(qkv_p, o_p);
    }

    // 4) proj + residual + repbn1
    {
        EpiParams p{};
        p.bias = b_proj; p.resid = t_p;
        p.gamma = gamma1; p.beta = beta1; p.rm = rm1; p.rv = rv1; p.alpha = alpha1;
        p.out = t2_p;
        gemm_tf32<1><<<dim3(CC/128, MROWS/128), 256>>>(o_p, W_proj, MROWS, CC, CC, p);
    }

    // 5) FFN up + SpatialSILU
    {
        EpiParams p{};
        p.bias = b1; p.saw = sa_w; p.sab = sa_b; p.out = h_p;
        gemm_tf32<2><<<dim3(CM/128, MROWS/128), 256>>>(t2_p, W1, MROWS, CM, CC, p);
    }

    // 6) FFN down + residual + repbn2
    {
        EpiParams p{};
        p.bias = b2; p.resid = t2_p;
        p.gamma = gamma2; p.beta = beta2; p.rm = rm2; p.rv = rv2; p.alpha = alpha2;
        p.out = t3_p;
        gemm_tf32<3><<<dim3(CC/128, MROWS/128), 256>>>(h_p, W2, MROWS, CC, CM, p);
    }

    // 7) t3 -> out
    transpose_out<<<tg, tb>>>(t3_p, out);
}

// round 4
// speedup vs baseline: 1.3428x; 1.3428x over previous
#include <cuda_runtime.h>
#include <cuda_bf16.h>
#include <mma.h>
#include <math.h>
#include <cstdint>

using namespace nvcuda;

// ---------------- problem constants ----------------
#define BB   256      // batch
#define CC   256      // channels
#define NN   196      // tokens (14*14)
#define NH   8        // heads
#define DD   32       // head dim
#define CM   2048     // ffn hidden
#define MROWS (BB*NN) // 50176
#define EPSBN 1e-5f

// ---------------- scratch (device globals; no allocations allowed) ----------------
__device__ float g_t [(size_t)MROWS*CC];      // tokens [B*N, C]
__device__ float g_qkv[(size_t)3*BB*NH*NN*DD]; // [part, b, h, n, d]
__device__ float g_o [(size_t)MROWS*CC];      // attention out [B*N, C]
__device__ float g_t2[(size_t)MROWS*CC];      // after repbn1
__device__ float g_h [(size_t)MROWS*CM];      // ffn hidden
__device__ float g_t3[(size_t)MROWS*CC];      // before final transpose

// ---------------- cp.async helpers ----------------
__device__ __forceinline__ void cp_async16(void* smem_dst, const void* gsrc)
{
    unsigned int s = (unsigned int)__cvta_generic_to_shared(smem_dst);
    asm volatile("cp.async.cg.shared.global [%0], [%1], 16;\n" :: "r"(s), "l"(gsrc));
}
__device__ __forceinline__ void cp_commit() { asm volatile("cp.async.commit_group;\n"); }
template <int N>
__device__ __forceinline__ void cp_wait() { asm volatile("cp.async.wait_group %0;\n" :: "n"(N)); }

// ---------------- transposes ----------------
__global__ void transpose_in(const float* __restrict__ x, float* __restrict__ t)
{
    __shared__ float tile[32][33];
    int b  = blockIdx.z;
    int n0 = blockIdx.x * 32;
    int c0 = blockIdx.y * 32;
    int tx = threadIdx.x, ty = threadIdx.y;
#pragma unroll
    for (int i = 0; i < 4; i++) {
        int c = c0 + ty + 8*i;
        int n = n0 + tx;
        if (n < NN) tile[ty + 8*i][tx] = x[((size_t)b*CC + c)*NN + n];
    }
    __syncthreads();
#pragma unroll
    for (int i = 0; i < 4; i++) {
        int n = n0 + ty + 8*i;
        int c = c0 + tx;
        if (n < NN) t[((size_t)b*NN + n)*CC + c] = tile[tx][ty + 8*i];
    }
}

__global__ void transpose_out(const float* __restrict__ t, float* __restrict__ x)
{
    __shared__ float tile[32][33];
    int b  = blockIdx.z;
    int n0 = blockIdx.x * 32;
    int c0 = blockIdx.y * 32;
    int tx = threadIdx.x, ty = threadIdx.y;
#pragma unroll
    for (int i = 0; i < 4; i++) {
        int n = n0 + ty + 8*i;
        int c = c0 + tx;
        if (n < NN) tile[ty + 8*i][tx] = t[((size_t)b*NN + n)*CC + c];
    }
    __syncthreads();
#pragma unroll
    for (int i = 0; i < 4; i++) {
        int c = c0 + ty + 8*i;
        int n = n0 + tx;
        if (n < NN) x[((size_t)b*CC + c)*NN + n] = tile[tx][ty + 8*i];
    }
}

// ---------------- epilogue params ----------------
struct EpiParams {
    const float* bias;
    const float* resid;
    const float* gamma;
    const float* beta;
    const float* rm;
    const float* rv;
    const float* alpha;  // scalar
    const float* saw;    // [B]
    const float* sab;    // [B]
    float*       out;
};

// EPI 0: qkv scatter  | EPI 1: proj + repbn1 | EPI 2: b1 + SpatialSILU | EPI 3: b2 + repbn2
template <int EPI>
__device__ __forceinline__ void apply_epi(int r, int c, float val, const EpiParams& p)
{
    if constexpr (EPI == 0) {
        val += p.bias[c];
        int part = c >> 8;
        int cc   = c & 255;
        int head = cc >> 5;
        int d    = cc & 31;
        int b    = r / NN;
        int n    = r - b * NN;
        size_t PS = (size_t)BB*NH*NN*DD;
        p.out[(size_t)part*PS + (((size_t)(b*NH + head))*NN + n)*DD + d] = val;
    } else if constexpr (EPI == 1 || EPI == 3) {
        val += p.bias[c];
        float tv = p.resid[(size_t)r*CC + c];
        float s  = p.gamma[c] * rsqrtf(p.rv[c] + EPSBN);
        float a  = p.alpha[0];
        float u  = tv + val;
        p.out[(size_t)r*CC + c] = u * (s + a) + (p.beta[c] - p.rm[c]*s);
    } else { // EPI == 2
        val += p.bias[c];
        int b = r / NN;
        float w  = p.saw[b];
        float sb = p.sab[b];
        float wg = w * val + sb;
        float sg = 1.0f / (1.0f + __expf(-wg * val));
        p.out[(size_t)r*CM + c] = val * sg;
    }
}

// ---------------- TF32 tiled GEMM, cp.async 2-stage pipelined ----------------
// block tile 128x128, K-step 32, 8 warps (2x4 wmma tiles of 16x16 per warp)
// dynamic smem: As[2][128][36] | Bs[2][32][132] | stage[8][256]
#define AS_STRIDE 36
#define BS_STRIDE 132
#define AS_FLOATS (128*AS_STRIDE)
#define BS_FLOATS (32*BS_STRIDE)
#define GEMM_SMEM_FLOATS (2*AS_FLOATS + 2*BS_FLOATS + 8*256)

template <int EPI>
__global__ __launch_bounds__(256, 2)
void gemm_tf32(const float* __restrict__ A, const float* __restrict__ Bm,
               int M, int N, int K, EpiParams p)
{
    extern __shared__ float sm[];
    float* As  = sm;                       // [2][128][36]
    float* Bs  = sm + 2*AS_FLOATS;         // [2][32][132]
    float* stg = sm + 2*AS_FLOATS + 2*BS_FLOATS; // [8][256]

    int tid  = threadIdx.x;
    int warp = tid >> 5;
    int lane = tid & 31;
    int wm   = warp >> 1;   // 0..3
    int wn   = warp & 1;    // 0..1
    int bn   = blockIdx.x;
    int bm   = blockIdx.y;
    size_t arow0 = (size_t)bm * 128;

    wmma::fragment<wmma::accumulator, 16, 16, 8, float> acc[2][4];
#pragma unroll
    for (int i = 0; i < 2; i++)
#pragma unroll
        for (int j = 0; j < 4; j++)
            wmma::fill_fragment(acc[i][j], 0.0f);

    // load-thread mapping
    int ar  = tid >> 3;          // 0..31  (A row within group of 32)
    int ac4 = (tid & 7) * 4;     // 0,4,...,28
    int br  = tid >> 5;          // 0..7   (B row within group of 8)
    int bc4 = (tid & 31) * 4;    // 0..124

    const float* Abase = A + arow0 * (size_t)K;
    const float* Bbase = Bm + (size_t)bn * 128;

    // async tile loader
    auto load_tile = [&](int stage, int k0) {
        float* Ad = As + stage * AS_FLOATS;
        float* Bd = Bs + stage * BS_FLOATS;
#pragma unroll
        for (int it = 0; it < 4; it++) {
            int row = ar + it*32;
            cp_async16(&Ad[row*AS_STRIDE + ac4], &Abase[(size_t)row*K + k0 + ac4]);
        }
#pragma unroll
        for (int it = 0; it < 4; it++) {
            int row = br + it*8;
            cp_async16(&Bd[row*BS_STRIDE + bc4], &Bbase[(size_t)(k0 + row)*N + bc4]);
        }
        cp_commit();
    };

    int ntiles = K >> 5;
    load_tile(0, 0);

    for (int t = 0; t < ntiles; t++) {
        int cur = t & 1;
        if (t + 1 < ntiles) {
            load_tile((t + 1) & 1, (t + 1) << 5);
            cp_wait<1>();
        } else {
            cp_wait<0>();
        }
        __syncthreads();

        float* Ac = As + cur * AS_FLOATS;
        float* Bc = Bs + cur * BS_FLOATS;
#pragma unroll
        for (int kk = 0; kk < 32; kk += 8) {
            wmma::fragment<wmma::matrix_a, 16, 16, 8, wmma::precision::tf32, wmma::row_major> af[2];
            wmma::fragment<wmma::matrix_b, 16, 16, 8, wmma::precision::tf32, wmma::row_major> bf[4];
#pragma unroll
            for (int i = 0; i < 2; i++) {
                wmma::load_matrix_sync(af[i], &Ac[(wm*32 + i*16)*AS_STRIDE + kk], AS_STRIDE);
#pragma unroll
                for (int e = 0; e < af[i].num_elements; e++)
                    af[i].x[e] = wmma::__float_to_tf32(af[i].x[e]);
            }
#pragma unroll
            for (int j = 0; j < 4; j++) {
                wmma::load_matrix_sync(bf[j], &Bc[kk*BS_STRIDE + wn*64 + j*16], BS_STRIDE);
#pragma unroll
                for (int e = 0; e < bf[j].num_elements; e++)
                    bf[j].x[e] = wmma::__float_to_tf32(bf[j].x[e]);
            }
#pragma unroll
            for (int i = 0; i < 2; i++)
#pragma unroll
                for (int j = 0; j < 4; j++)
                    wmma::mma_sync(acc[i][j], af[i], bf[j], acc[i][j]);
        }
        __syncthreads();
    }

    // epilogue via per-warp staging
    float* stw = stg + warp * 256;
#pragma unroll
    for (int i = 0; i < 2; i++) {
#pragma unroll
        for (int j = 0; j < 4; j++) {
            wmma::store_matrix_sync(stw, acc[i][j], 16, wmma::mem_row_major);
            __syncwarp();
            int r0 = bm*128 + wm*32 + i*16;
            int c0 = bn*128 + wn*64 + j*16;
#pragma unroll
            for (int q = 0; q < 8; q++) {
                int e  = lane*8 + q;
                int rr = e >> 4;
                int cc = e & 15;
                apply_epi<EPI>(r0 + rr, c0 + cc, stw[e], p);
            }
            __syncwarp();
        }
    }
}

// ---------------- attention: one block per (b, head) ----------------
// smem: kst[32][196] (K transposed), vs[196][32], qs[8][4][32], ps[8][196][4]
#define ATTN_SMEM_FLOATS (32*196 + 196*32 + 8*4*32 + 8*196*4)

__global__ __launch_bounds__(256)
void attn_kernel(const float* __restrict__ qkv, float* __restrict__ o)
{
    extern __shared__ float sm[];
    float* kst = sm;                    // [d][j]  d*196 + j
    float* vs  = sm + 32*196;           // [j][d]  j*32 + d
    float* qs  = sm + 2*32*196;         // [w][4][32]
    float* ps  = qs + 8*4*32;           // [w][196][4]

    int bh = blockIdx.x;
    int b  = bh >> 3;
    int h  = bh & 7;
    int tid  = threadIdx.x;
    int w    = tid >> 5;
    int lane = tid & 31;

    size_t PS = (size_t)BB*NH*NN*DD;
    const float* qp = qkv + ((size_t)(b*NH + h))*NN*DD;
    const float* kp = qp + PS;
    const float* vp = qp + 2*PS;

    // load K transposed + V straight
    for (int idx = tid; idx < NN*DD; idx += 256) {
        int j = idx >> 5;
        int d = idx & 31;
        float kv = kp[idx];
        kst[d*NN + j] = kv;
        vs[idx] = vp[idx];
    }
    __syncthreads();

    const float scale = 0.1767766952966369f; // 32^-0.5
    float* qsw = qs + w*128;
    float* psw = ps + w*784;

    int jidx[7]; bool jok[7];
#pragma unroll
    for (int jj = 0; jj < 7; jj++) { jidx[jj] = lane + 32*jj; jok[jj] = jidx[jj] < NN; }

    for (int g = w; g < 49; g += 8) {
        int r0 = g * 4;
#pragma unroll
        for (int t = 0; t < 4; t++)
            qsw[t*32 + lane] = qp[(size_t)(r0 + t)*DD + lane];
        __syncwarp();

        float s[7][4];
#pragma unroll
        for (int jj = 0; jj < 7; jj++)
#pragma unroll
            for (int r = 0; r < 4; r++) s[jj][r] = 0.0f;

        for (int d = 0; d < 32; d++) {
            float qv0 = qsw[0*32 + d];
            float qv1 = qsw[1*32 + d];
            float qv2 = qsw[2*32 + d];
            float qv3 = qsw[3*32 + d];
            const float* krow = &kst[d*NN];
#pragma unroll
            for (int jj = 0; jj < 7; jj++) {
                float kv = jok[jj] ? krow[jidx[jj]] : 0.0f;
                s[jj][0] += qv0 * kv;
                s[jj][1] += qv1 * kv;
                s[jj][2] += qv2 * kv;
                s[jj][3] += qv3 * kv;
            }
        }

#pragma unroll
        for (int r = 0; r < 4; r++) {
            float mx = -INFINITY;
#pragma unroll
            for (int jj = 0; jj < 7; jj++) {
                float sv = jok[jj] ? s[jj][r] * scale : -INFINITY;
                s[jj][r] = sv;
                mx = fmaxf(mx, sv);
            }
#pragma unroll
            for (int off = 16; off > 0; off >>= 1)
                mx = fmaxf(mx, __shfl_xor_sync(0xFFFFFFFFu, mx, off));
            float sum = 0.0f;
#pragma unroll
            for (int jj = 0; jj < 7; jj++) {
                float e = jok[jj] ? __expf(s[jj][r] - mx) : 0.0f;
                s[jj][r] = e;
                sum += e;
            }
#pragma unroll
            for (int off = 16; off > 0; off >>= 1)
                sum += __shfl_xor_sync(0xFFFFFFFFu, sum, off);
            float inv = 1.0f / sum;
#pragma unroll
            for (int jj = 0; jj < 7; jj++)
                if (jok[jj]) psw[jidx[jj]*4 + r] = s[jj][r] * inv;
        }
        __syncwarp();

        float a0 = 0.f, a1 = 0.f, a2 = 0.f, a3 = 0.f;
#pragma unroll 4
        for (int j = 0; j < NN; j++) {
            float4 pv = *(const float4*)&psw[j*4];
            float vv = vs[j*32 + lane];
            a0 += pv.x * vv;
            a1 += pv.y * vv;
            a2 += pv.z * vv;
            a3 += pv.w * vv;
        }
        size_t ob = ((size_t)b*NN + r0)*CC + h*DD + lane;
        o[ob + 0*CC] = a0;
        o[ob + 1*CC] = a1;
        o[ob + 2*CC] = a2;
        o[ob + 3*CC] = a3;
        __syncwarp();
    }
}

// ---------------- launch ----------------
extern "C" void kernel_launch(void* const* d_in, const int* in_sizes, int n_in,
                              void* d_out, int out_size)
{
    const float* x      = (const float*)d_in[0];
    const float* W_qkv  = (const float*)d_in[1];
    const float* b_qkv  = (const float*)d_in[2];
    const float* W_proj = (const float*)d_in[3];
    const float* b_proj = (const float*)d_in[4];
    const float* W1     = (const float*)d_in[5];
    const float* b1     = (const float*)d_in[6];
    const float* W2     = (const float*)d_in[7];
    const float* b2     = (const float*)d_in[8];
    const float* sa_w   = (const float*)d_in[9];
    const float* sa_b   = (const float*)d_in[10];
    const float* alpha1 = (const float*)d_in[11];
    const float* gamma1 = (const float*)d_in[12];
    const float* beta1  = (const float*)d_in[13];
    const float* rm1    = (const float*)d_in[14];
    const float* rv1    = (const float*)d_in[15];
    const float* alpha2 = (const float*)d_in[16];
    const float* gamma2 = (const float*)d_in[17];
    const float* beta2  = (const float*)d_in[18];
    const float* rm2    = (const float*)d_in[19];
    const float* rv2    = (const float*)d_in[20];
    float* out = (float*)d_out;

    float *t_p, *qkv_p, *o_p, *t2_p, *h_p, *t3_p;
    cudaGetSymbolAddress((void**)&t_p,   g_t);
    cudaGetSymbolAddress((void**)&qkv_p, g_qkv);
    cudaGetSymbolAddress((void**)&o_p,   g_o);
    cudaGetSymbolAddress((void**)&t2_p,  g_t2);
    cudaGetSymbolAddress((void**)&h_p,   g_h);
    cudaGetSymbolAddress((void**)&t3_p,  g_t3);

    int gemm_smem = GEMM_SMEM_FLOATS * 4;
    cudaFuncSetAttribute(gemm_tf32<0>, cudaFuncAttributeMaxDynamicSharedMemorySize, gemm_smem);
    cudaFuncSetAttribute(gemm_tf32<1>, cudaFuncAttributeMaxDynamicSharedMemorySize, gemm_smem);
    cudaFuncSetAttribute(gemm_tf32<2>, cudaFuncAttributeMaxDynamicSharedMemorySize, gemm_smem);
    cudaFuncSetAttribute(gemm_tf32<3>, cudaFuncAttributeMaxDynamicSharedMemorySize, gemm_smem);

    dim3 tb(32, 8);
    dim3 tg(7, 8, BB);

    // 1) x -> t
    transpose_in<<<tg, tb>>>(x, t_p);

    // 2) qkv GEMM (scatter epilogue)
    {
        EpiParams p{};
        p.bias = b_qkv; p.out = qkv_p;
        gemm_tf32<0><<<dim3(768/128, MROWS/128), 256, gemm_smem>>>(t_p, W_qkv, MROWS, 768, CC, p);
    }

    // 3) attention
    {
        int smem_bytes = ATTN_SMEM_FLOATS * 4;
        cudaFuncSetAttribute(attn_kernel, cudaFuncAttributeMaxDynamicSharedMemorySize, smem_bytes);
        attn_kernel<<<BB*NH, 256, smem_bytes>>>(qkv_p, o_p);
    }

    // 4) proj + residual + repbn1
    {
        EpiParams p{};
        p.bias = b_proj; p.resid = t_p;
        p.gamma = gamma1; p.beta = beta1; p.rm = rm1; p.rv = rv1; p.alpha = alpha1;
        p.out = t2_p;
        gemm_tf32<1><<<dim3(CC/128, MROWS/128), 256, gemm_smem>>>(o_p, W_proj, MROWS, CC, CC, p);
    }

    // 5) FFN up + SpatialSILU
    {
        EpiParams p{};
        p.bias = b1; p.saw = sa_w; p.sab = sa_b; p.out = h_p;
        gemm_tf32<2><<<dim3(CM/128, MROWS/128), 256, gemm_smem>>>(t2_p, W1, MROWS, CM, CC, p);
    }

    // 6) FFN down + residual + repbn2
    {
        EpiParams p{};
        p.bias = b2; p.resid = t2_p;
        p.gamma = gamma2; p.beta = beta2; p.rm = rm2; p.rv = rv2; p.alpha = alpha2;
        p.out = t3_p;
        gemm_tf32<3><<<dim3(CC/128, MROWS/128), 256, gemm_smem>>>(h_p, W2, MROWS, CC, CM, p);
    }

    // 7) t3 -> out
    transpose_out<<<tg, tb>>>(t3_p, out);
}